// round 10
// baseline (speedup 1.0000x reference)
#include <cuda_runtime.h>
#include <cstdint>

#define F_DIM 64
#define F_VEC 16            // 64 floats = 16 float4
#define MAX_NODES 100000
#define CAP 64              // bucket capacity per node (deg ~ Poisson(8))
#define CAP_SHIFT 6
#define SEG_BLOCKS 1184     // 148 SMs x 8 blocks: fully resident persistent grid
#define SEG_THREADS 256

// Scratch (no allocation allowed). Zero-initialized; slots beyond a node's
// degree are never written (degrees identical every replay), so speculative
// gathers through them read row 0 (valid memory, add predicated off).
__device__ int g_cursor[MAX_NODES];           // per-node fill cursor == degree
__device__ int g_bucket[MAX_NODES * CAP];     // src ids bucketed by tgt (25.6MB)

// ---------------------------------------------------------------------------
// K1: bucket scatter of src ids by tgt. 4 edges/thread via int4 loads.
// start[t] implicit (t*CAP): no count pass, no prefix scan.
// ---------------------------------------------------------------------------
__global__ void k_sortsrc(const int4* __restrict__ src4,
                          const int4* __restrict__ tgt4,
                          int* __restrict__ cursor,
                          int* __restrict__ bucket,
                          int n_groups) {
    int g = blockIdx.x * blockDim.x + threadIdx.x;
    if (g < n_groups) {
        int4 s = src4[g];
        int4 t = tgt4[g];
        int p0 = atomicAdd(&cursor[t.x], 1);
        int p1 = atomicAdd(&cursor[t.y], 1);
        int p2 = atomicAdd(&cursor[t.z], 1);
        int p3 = atomicAdd(&cursor[t.w], 1);
        bucket[(t.x << CAP_SHIFT) + p0] = s.x;
        bucket[(t.y << CAP_SHIFT) + p1] = s.y;
        bucket[(t.z << CAP_SHIFT) + p2] = s.z;
        bucket[(t.w << CAP_SHIFT) + p3] = s.w;
    }
}

// ---------------------------------------------------------------------------
// Gather+accumulate one node's (<=16) neighbors from resident indices.
// First 8 gathers speculative (adds masked), 8..15 predicated, tail loop rare.
// ---------------------------------------------------------------------------
__device__ __forceinline__ float4 node_sum(const float4* __restrict__ x4,
                                           const int4* __restrict__ seg,
                                           int c, int4 i0, int4 i1,
                                           int4 i2, int4 i3, int lane) {
    float4 acc = make_float4(0.f, 0.f, 0.f, 0.f);

    float4 a0 = __ldg(&x4[(size_t)i0.x * F_VEC + lane]);
    float4 a1 = __ldg(&x4[(size_t)i0.y * F_VEC + lane]);
    float4 a2 = __ldg(&x4[(size_t)i0.z * F_VEC + lane]);
    float4 a3 = __ldg(&x4[(size_t)i0.w * F_VEC + lane]);
    float4 a4 = __ldg(&x4[(size_t)i1.x * F_VEC + lane]);
    float4 a5 = __ldg(&x4[(size_t)i1.y * F_VEC + lane]);
    float4 a6 = __ldg(&x4[(size_t)i1.z * F_VEC + lane]);
    float4 a7 = __ldg(&x4[(size_t)i1.w * F_VEC + lane]);
    if (c > 0) { acc.x += a0.x; acc.y += a0.y; acc.z += a0.z; acc.w += a0.w; }
    if (c > 1) { acc.x += a1.x; acc.y += a1.y; acc.z += a1.z; acc.w += a1.w; }
    if (c > 2) { acc.x += a2.x; acc.y += a2.y; acc.z += a2.z; acc.w += a2.w; }
    if (c > 3) { acc.x += a3.x; acc.y += a3.y; acc.z += a3.z; acc.w += a3.w; }
    if (c > 4) { acc.x += a4.x; acc.y += a4.y; acc.z += a4.z; acc.w += a4.w; }
    if (c > 5) { acc.x += a5.x; acc.y += a5.y; acc.z += a5.z; acc.w += a5.w; }
    if (c > 6) { acc.x += a6.x; acc.y += a6.y; acc.z += a6.z; acc.w += a6.w; }
    if (c > 7) { acc.x += a7.x; acc.y += a7.y; acc.z += a7.z; acc.w += a7.w; }

    if (c > 8) {
        if (c > 8)  { float4 a = __ldg(&x4[(size_t)i2.x * F_VEC + lane]);
                      acc.x += a.x; acc.y += a.y; acc.z += a.z; acc.w += a.w; }
        if (c > 9)  { float4 a = __ldg(&x4[(size_t)i2.y * F_VEC + lane]);
                      acc.x += a.x; acc.y += a.y; acc.z += a.z; acc.w += a.w; }
        if (c > 10) { float4 a = __ldg(&x4[(size_t)i2.z * F_VEC + lane]);
                      acc.x += a.x; acc.y += a.y; acc.z += a.z; acc.w += a.w; }
        if (c > 11) { float4 a = __ldg(&x4[(size_t)i2.w * F_VEC + lane]);
                      acc.x += a.x; acc.y += a.y; acc.z += a.z; acc.w += a.w; }
        if (c > 12) { float4 a = __ldg(&x4[(size_t)i3.x * F_VEC + lane]);
                      acc.x += a.x; acc.y += a.y; acc.z += a.z; acc.w += a.w; }
        if (c > 13) { float4 a = __ldg(&x4[(size_t)i3.y * F_VEC + lane]);
                      acc.x += a.x; acc.y += a.y; acc.z += a.z; acc.w += a.w; }
        if (c > 14) { float4 a = __ldg(&x4[(size_t)i3.z * F_VEC + lane]);
                      acc.x += a.x; acc.y += a.y; acc.z += a.z; acc.w += a.w; }
        if (c > 15) { float4 a = __ldg(&x4[(size_t)i3.w * F_VEC + lane]);
                      acc.x += a.x; acc.y += a.y; acc.z += a.z; acc.w += a.w; }
        // deg > 16: rare tail (~0.4% of nodes)
        for (int base = 16; base < c; base += 4) {
            int4 j = __ldg(&seg[base >> 2]);
            if (base + 0 < c) { float4 a = __ldg(&x4[(size_t)j.x * F_VEC + lane]);
                                acc.x += a.x; acc.y += a.y; acc.z += a.z; acc.w += a.w; }
            if (base + 1 < c) { float4 a = __ldg(&x4[(size_t)j.y * F_VEC + lane]);
                                acc.x += a.x; acc.y += a.y; acc.z += a.z; acc.w += a.w; }
            if (base + 2 < c) { float4 a = __ldg(&x4[(size_t)j.z * F_VEC + lane]);
                                acc.x += a.x; acc.y += a.y; acc.z += a.z; acc.w += a.w; }
            if (base + 3 < c) { float4 a = __ldg(&x4[(size_t)j.w * F_VEC + lane]);
                                acc.x += a.x; acc.y += a.y; acc.z += a.z; acc.w += a.w; }
        }
    }
    return acc;
}

// ---------------------------------------------------------------------------
// K2: persistent segmented mean with cross-node software pipelining.
// 16 threads per node; each group strides over nodes. While gathering node i,
// the cursor + index loads for node i+stride are already in flight, so
// steady-state exposes only the gather latency hop.
// ---------------------------------------------------------------------------
__global__ void k_seg(const float4* __restrict__ x4,
                      const int* __restrict__ bucket,
                      const int* __restrict__ cursor,
                      float4* __restrict__ out4,
                      int n_nodes) {
    int gtid   = blockIdx.x * blockDim.x + threadIdx.x;
    int group  = gtid >> 4;
    int lane   = gtid & 15;
    int stride = (gridDim.x * blockDim.x) >> 4;

    int node = group;
    if (node >= n_nodes) return;

    // prologue: loads for first node
    const int4* seg = (const int4*)(bucket + ((size_t)node << CAP_SHIFT));
    int  c  = __ldg(&cursor[node]);
    int4 i0 = __ldg(&seg[0]);
    int4 i1 = __ldg(&seg[1]);
    int4 i2 = __ldg(&seg[2]);
    int4 i3 = __ldg(&seg[3]);

    while (true) {
        int next = node + stride;
        bool has_next = next < n_nodes;

        // prefetch next node's metadata while current gathers are in flight
        const int4* seg_n = (const int4*)(bucket + ((size_t)next << CAP_SHIFT));
        int  c_n = 0;
        int4 j0 = make_int4(0,0,0,0), j1 = j0, j2 = j0, j3 = j0;
        if (has_next) {
            c_n = __ldg(&cursor[next]);
            j0  = __ldg(&seg_n[0]);
            j1  = __ldg(&seg_n[1]);
            j2  = __ldg(&seg_n[2]);
            j3  = __ldg(&seg_n[3]);
        }

        float4 acc = node_sum(x4, seg, c, i0, i1, i2, i3, lane);

        float w = 1.0f / (float)(c > 0 ? c : 1);
        acc.x *= w; acc.y *= w; acc.z *= w; acc.w *= w;
        out4[(size_t)node * F_VEC + lane] = acc;

        if (!has_next) break;
        node = next; seg = seg_n;
        c = c_n; i0 = j0; i1 = j1; i2 = j2; i3 = j3;
    }
}

// ---------------------------------------------------------------------------
// Launch
// ---------------------------------------------------------------------------
extern "C" void kernel_launch(void* const* d_in, const int* in_sizes, int n_in,
                              void* d_out, int out_size) {
    const float* x   = (const float*)d_in[0];
    const int*   src = (const int*)d_in[1];
    const int*   tgt = (const int*)d_in[2];
    float*       out = (float*)d_out;

    int n_nodes  = in_sizes[0] / F_DIM;   // 100000
    int n_edges  = in_sizes[1];           // 800000
    int n_groups = n_edges / 4;

    int *cursor, *bucket;
    cudaGetSymbolAddress((void**)&cursor, g_cursor);
    cudaGetSymbolAddress((void**)&bucket, g_bucket);

    const int B = 256;

    cudaMemsetAsync(cursor, 0, (size_t)n_nodes * sizeof(int));
    k_sortsrc<<<(n_groups + B - 1) / B, B>>>((const int4*)src, (const int4*)tgt,
                                             cursor, bucket, n_groups);
    {
        // persistent grid: don't exceed the work itself
        long long need_groups = n_nodes;
        int max_blocks = (int)((need_groups * F_VEC + SEG_THREADS - 1) / SEG_THREADS);
        int grid = SEG_BLOCKS < max_blocks ? SEG_BLOCKS : max_blocks;
        k_seg<<<grid, SEG_THREADS>>>((const float4*)x, bucket, cursor,
                                     (float4*)out, n_nodes);
    }
}

// round 11
// speedup vs baseline: 1.2009x; 1.2009x over previous
#include <cuda_runtime.h>
#include <cstdint>

#define F_DIM 64
#define F_VEC2 32           // 64 floats = 32 float2; lane l owns float2 #l
#define MAX_NODES 100000
#define CAP 64              // bucket capacity per node (deg ~ Poisson(8))
#define CAP_SHIFT 6

// Scratch (no allocation allowed). Zero-initialized; slots beyond a node's
// degree are never written (degrees identical every replay).
__device__ int g_cursor[MAX_NODES];           // per-node fill cursor == degree
__device__ int g_bucket[MAX_NODES * CAP];     // src ids bucketed by tgt (25.6MB)

// ---------------------------------------------------------------------------
// K1: bucket scatter of src ids by tgt. 4 edges/thread via int4 loads.
// start[t] implicit (t*CAP): no count pass, no prefix scan.
// ---------------------------------------------------------------------------
__global__ void k_sortsrc(const int4* __restrict__ src4,
                          const int4* __restrict__ tgt4,
                          int* __restrict__ cursor,
                          int* __restrict__ bucket,
                          int n_groups) {
    int g = blockIdx.x * blockDim.x + threadIdx.x;
    if (g < n_groups) {
        int4 s = src4[g];
        int4 t = tgt4[g];
        int p0 = atomicAdd(&cursor[t.x], 1);
        int p1 = atomicAdd(&cursor[t.y], 1);
        int p2 = atomicAdd(&cursor[t.z], 1);
        int p3 = atomicAdd(&cursor[t.w], 1);
        bucket[(t.x << CAP_SHIFT) + p0] = s.x;
        bucket[(t.y << CAP_SHIFT) + p1] = s.y;
        bucket[(t.z << CAP_SHIFT) + p2] = s.z;
        bucket[(t.w << CAP_SHIFT) + p3] = s.w;
    }
}

// ---------------------------------------------------------------------------
// K2: segmented mean, ONE WARP PER NODE.
// Lane l owns float2 #l of the 64-float row (32 x 8B = 256B per gather
// instruction). All 32 lanes share the node's degree -> fully uniform
// control flow, no predication waste, per-warp runtime = own node only.
// 8 independent gathers per iteration (two broadcast int4 index loads).
// ---------------------------------------------------------------------------
__global__ void __launch_bounds__(256) k_seg(
        const float2* __restrict__ x2,
        const int* __restrict__ bucket,
        const int* __restrict__ cursor,
        float2* __restrict__ out2,
        int n_nodes) {
    int node = (blockIdx.x * blockDim.x + threadIdx.x) >> 5;
    int lane = threadIdx.x & 31;
    if (node >= n_nodes) return;

    const int4* seg = (const int4*)(bucket + ((size_t)node << CAP_SHIFT));
    int c = __ldg(&cursor[node]);

    float2 acc = make_float2(0.f, 0.f);

    for (int base = 0; base < c; base += 8) {
        int q = base >> 2;
        int4 i0 = __ldg(&seg[q]);       // broadcast: indices base..base+3
        int4 i1 = __ldg(&seg[q + 1]);   // broadcast: indices base+4..base+7

        if (base + 0 < c) { float2 a = __ldg(&x2[(size_t)i0.x * F_VEC2 + lane]);
                            acc.x += a.x; acc.y += a.y; }
        if (base + 1 < c) { float2 a = __ldg(&x2[(size_t)i0.y * F_VEC2 + lane]);
                            acc.x += a.x; acc.y += a.y; }
        if (base + 2 < c) { float2 a = __ldg(&x2[(size_t)i0.z * F_VEC2 + lane]);
                            acc.x += a.x; acc.y += a.y; }
        if (base + 3 < c) { float2 a = __ldg(&x2[(size_t)i0.w * F_VEC2 + lane]);
                            acc.x += a.x; acc.y += a.y; }
        if (base + 4 < c) { float2 a = __ldg(&x2[(size_t)i1.x * F_VEC2 + lane]);
                            acc.x += a.x; acc.y += a.y; }
        if (base + 5 < c) { float2 a = __ldg(&x2[(size_t)i1.y * F_VEC2 + lane]);
                            acc.x += a.x; acc.y += a.y; }
        if (base + 6 < c) { float2 a = __ldg(&x2[(size_t)i1.z * F_VEC2 + lane]);
                            acc.x += a.x; acc.y += a.y; }
        if (base + 7 < c) { float2 a = __ldg(&x2[(size_t)i1.w * F_VEC2 + lane]);
                            acc.x += a.x; acc.y += a.y; }
    }

    float w = 1.0f / (float)(c > 0 ? c : 1);
    acc.x *= w; acc.y *= w;
    out2[(size_t)node * F_VEC2 + lane] = acc;
}

// ---------------------------------------------------------------------------
// Launch
// ---------------------------------------------------------------------------
extern "C" void kernel_launch(void* const* d_in, const int* in_sizes, int n_in,
                              void* d_out, int out_size) {
    const float* x   = (const float*)d_in[0];
    const int*   src = (const int*)d_in[1];
    const int*   tgt = (const int*)d_in[2];
    float*       out = (float*)d_out;

    int n_nodes  = in_sizes[0] / F_DIM;   // 100000
    int n_edges  = in_sizes[1];           // 800000
    int n_groups = n_edges / 4;

    int *cursor, *bucket;
    cudaGetSymbolAddress((void**)&cursor, g_cursor);
    cudaGetSymbolAddress((void**)&bucket, g_bucket);

    const int B = 256;

    cudaMemsetAsync(cursor, 0, (size_t)n_nodes * sizeof(int));
    k_sortsrc<<<(n_groups + B - 1) / B, B>>>((const int4*)src, (const int4*)tgt,
                                             cursor, bucket, n_groups);
    {
        // one warp per node
        long long threads = (long long)n_nodes * 32;
        int grid = (int)((threads + B - 1) / B);
        k_seg<<<grid, B>>>((const float2*)x, bucket, cursor,
                           (float2*)out, n_nodes);
    }
}

// round 12
// speedup vs baseline: 1.2580x; 1.0475x over previous
#include <cuda_runtime.h>
#include <cstdint>

#define F_DIM 64
#define F_VEC4 16           // 64 floats = 16 float4
#define MAX_NODES 100000
#define CAP 64              // bucket capacity per node (deg ~ Poisson(8))
#define CAP_SHIFT 6

// Scratch (no allocation allowed). Zero-initialized; slots beyond a node's
// degree are never written (degrees identical every replay).
__device__ int g_cursor[MAX_NODES];           // per-node fill cursor == degree
__device__ int g_bucket[MAX_NODES * CAP];     // src ids bucketed by tgt (25.6MB)

// ---------------------------------------------------------------------------
// K1: bucket scatter of src ids by tgt. 4 edges/thread via int4 loads.
// start[t] implicit (t*CAP): no count pass, no prefix scan.
// ---------------------------------------------------------------------------
__global__ void k_sortsrc(const int4* __restrict__ src4,
                          const int4* __restrict__ tgt4,
                          int* __restrict__ cursor,
                          int* __restrict__ bucket,
                          int n_groups) {
    int g = blockIdx.x * blockDim.x + threadIdx.x;
    if (g < n_groups) {
        int4 s = src4[g];
        int4 t = tgt4[g];
        int p0 = atomicAdd(&cursor[t.x], 1);
        int p1 = atomicAdd(&cursor[t.y], 1);
        int p2 = atomicAdd(&cursor[t.z], 1);
        int p3 = atomicAdd(&cursor[t.w], 1);
        bucket[(t.x << CAP_SHIFT) + p0] = s.x;
        bucket[(t.y << CAP_SHIFT) + p1] = s.y;
        bucket[(t.z << CAP_SHIFT) + p2] = s.z;
        bucket[(t.w << CAP_SHIFT) + p3] = s.w;
    }
}

// ---------------------------------------------------------------------------
// K2: segmented mean, ONE WARP PER NODE, half-warp edge pairing.
// Lanes 0-15 gather even edges' float4 columns, lanes 16-31 odd edges':
// one LDG.128 warp instruction covers TWO 256B feature rows. Loop bounds
// are warp-uniform (shared degree); only the tail predicate differs between
// halves -> predication, no branches. Halves combined via shfl_xor(16).
// ---------------------------------------------------------------------------
__global__ void __launch_bounds__(256) k_seg(
        const float4* __restrict__ x4,
        const int* __restrict__ bucket,
        const int* __restrict__ cursor,
        float4* __restrict__ out4,
        int n_nodes) {
    int node = (blockIdx.x * blockDim.x + threadIdx.x) >> 5;
    int lane = threadIdx.x & 31;
    int half = lane >> 4;          // 0: even edges, 1: odd edges
    int l16  = lane & 15;          // float4 column within the row
    if (node >= n_nodes) return;

    const int4* seg = (const int4*)(bucket + ((size_t)node << CAP_SHIFT));
    int c = __ldg(&cursor[node]);

    float4 acc = make_float4(0.f, 0.f, 0.f, 0.f);

    for (int base = 0; base < c; base += 8) {
        int q = base >> 2;
        int4 i0 = __ldg(&seg[q]);       // broadcast: edges base..base+3
        int4 i1 = __ldg(&seg[q + 1]);   // broadcast: edges base+4..base+7

        // this lane's edge in each of the 4 pairs
        int e  = base + half;           // pair 0 handles edges e, e+2, e+4, e+6
        int s0 = half ? i0.y : i0.x;
        int s1 = half ? i0.w : i0.z;
        int s2 = half ? i1.y : i1.x;
        int s3 = half ? i1.w : i1.z;

        // 32-bit offsets (idx*16+l16 < 2^21): avoids 64-bit IMAD chains
        if (e     < c) { float4 a = __ldg(&x4[s0 * F_VEC4 + l16]);
                         acc.x += a.x; acc.y += a.y; acc.z += a.z; acc.w += a.w; }
        if (e + 2 < c) { float4 a = __ldg(&x4[s1 * F_VEC4 + l16]);
                         acc.x += a.x; acc.y += a.y; acc.z += a.z; acc.w += a.w; }
        if (e + 4 < c) { float4 a = __ldg(&x4[s2 * F_VEC4 + l16]);
                         acc.x += a.x; acc.y += a.y; acc.z += a.z; acc.w += a.w; }
        if (e + 6 < c) { float4 a = __ldg(&x4[s3 * F_VEC4 + l16]);
                         acc.x += a.x; acc.y += a.y; acc.z += a.z; acc.w += a.w; }
    }

    // combine the two halves (same column l16, different edge subsets)
    acc.x += __shfl_xor_sync(0xFFFFFFFFu, acc.x, 16);
    acc.y += __shfl_xor_sync(0xFFFFFFFFu, acc.y, 16);
    acc.z += __shfl_xor_sync(0xFFFFFFFFu, acc.z, 16);
    acc.w += __shfl_xor_sync(0xFFFFFFFFu, acc.w, 16);

    float w = 1.0f / (float)(c > 0 ? c : 1);
    acc.x *= w; acc.y *= w; acc.z *= w; acc.w *= w;

    if (half == 0)
        out4[node * F_VEC4 + l16] = acc;   // half-warp ST.128: 256B/node
}

// ---------------------------------------------------------------------------
// Launch
// ---------------------------------------------------------------------------
extern "C" void kernel_launch(void* const* d_in, const int* in_sizes, int n_in,
                              void* d_out, int out_size) {
    const float* x   = (const float*)d_in[0];
    const int*   src = (const int*)d_in[1];
    const int*   tgt = (const int*)d_in[2];
    float*       out = (float*)d_out;

    int n_nodes  = in_sizes[0] / F_DIM;   // 100000
    int n_edges  = in_sizes[1];           // 800000
    int n_groups = n_edges / 4;

    int *cursor, *bucket;
    cudaGetSymbolAddress((void**)&cursor, g_cursor);
    cudaGetSymbolAddress((void**)&bucket, g_bucket);

    const int B = 256;

    cudaMemsetAsync(cursor, 0, (size_t)n_nodes * sizeof(int));
    k_sortsrc<<<(n_groups + B - 1) / B, B>>>((const int4*)src, (const int4*)tgt,
                                             cursor, bucket, n_groups);
    {
        // one warp per node
        long long threads = (long long)n_nodes * 32;
        int grid = (int)((threads + B - 1) / B);
        k_seg<<<grid, B>>>((const float4*)x, bucket, cursor,
                           (float4*)out, n_nodes);
    }
}

// round 13
// speedup vs baseline: 1.2632x; 1.0041x over previous
#include <cuda_runtime.h>
#include <cstdint>

#define F_DIM 64
#define F_VEC4 16           // 64 floats = 16 float4
#define MAX_NODES 100000
#define CAP 64              // bucket capacity per node (deg ~ Poisson(8))
#define CAP_SHIFT 6

// Scratch (no allocation allowed). Zero-initialized; slots beyond a node's
// degree are never written (degrees identical every replay).
__device__ int g_cursor[MAX_NODES];           // per-node fill cursor == degree
__device__ int g_bucket[MAX_NODES * CAP];     // src ids bucketed by tgt (25.6MB)

// ---------------------------------------------------------------------------
// K1: bucket scatter of src ids by tgt. 8 edges/thread via two int4 pairs:
// deeper atomic/store MLP per thread.
// ---------------------------------------------------------------------------
__global__ void k_sortsrc(const int4* __restrict__ src4,
                          const int4* __restrict__ tgt4,
                          int* __restrict__ cursor,
                          int* __restrict__ bucket,
                          int n_groups) {
    int g = (blockIdx.x * blockDim.x + threadIdx.x) * 2;
    if (g >= n_groups) return;

    int4 s0 = src4[g];
    int4 t0 = tgt4[g];
    bool two = (g + 1) < n_groups;
    int4 s1 = two ? src4[g + 1] : make_int4(0, 0, 0, 0);
    int4 t1 = two ? tgt4[g + 1] : make_int4(0, 0, 0, 0);

    int p0 = atomicAdd(&cursor[t0.x], 1);
    int p1 = atomicAdd(&cursor[t0.y], 1);
    int p2 = atomicAdd(&cursor[t0.z], 1);
    int p3 = atomicAdd(&cursor[t0.w], 1);
    int p4 = two ? atomicAdd(&cursor[t1.x], 1) : 0;
    int p5 = two ? atomicAdd(&cursor[t1.y], 1) : 0;
    int p6 = two ? atomicAdd(&cursor[t1.z], 1) : 0;
    int p7 = two ? atomicAdd(&cursor[t1.w], 1) : 0;

    bucket[(t0.x << CAP_SHIFT) + p0] = s0.x;
    bucket[(t0.y << CAP_SHIFT) + p1] = s0.y;
    bucket[(t0.z << CAP_SHIFT) + p2] = s0.z;
    bucket[(t0.w << CAP_SHIFT) + p3] = s0.w;
    if (two) {
        bucket[(t1.x << CAP_SHIFT) + p4] = s1.x;
        bucket[(t1.y << CAP_SHIFT) + p5] = s1.y;
        bucket[(t1.z << CAP_SHIFT) + p6] = s1.z;
        bucket[(t1.w << CAP_SHIFT) + p7] = s1.w;
    }
}

// ---------------------------------------------------------------------------
// Per-node gather body (warp-uniform, half-warp edge pairing).
// Lanes 0-15 = even edges, 16-31 = odd edges: one LDG.128 covers two rows.
// ---------------------------------------------------------------------------
__device__ __forceinline__ float4 gather8(const float4* __restrict__ x4,
                                          int4 i0, int4 i1, int c,
                                          int half, int l16) {
    float4 acc = make_float4(0.f, 0.f, 0.f, 0.f);
    int e  = half;                 // this lane's first edge (0 or 1)
    int s0 = half ? i0.y : i0.x;
    int s1 = half ? i0.w : i0.z;
    int s2 = half ? i1.y : i1.x;
    int s3 = half ? i1.w : i1.z;
    if (e     < c) { float4 a = __ldg(&x4[s0 * F_VEC4 + l16]);
                     acc.x += a.x; acc.y += a.y; acc.z += a.z; acc.w += a.w; }
    if (e + 2 < c) { float4 a = __ldg(&x4[s1 * F_VEC4 + l16]);
                     acc.x += a.x; acc.y += a.y; acc.z += a.z; acc.w += a.w; }
    if (e + 4 < c) { float4 a = __ldg(&x4[s2 * F_VEC4 + l16]);
                     acc.x += a.x; acc.y += a.y; acc.z += a.z; acc.w += a.w; }
    if (e + 6 < c) { float4 a = __ldg(&x4[s3 * F_VEC4 + l16]);
                     acc.x += a.x; acc.y += a.y; acc.z += a.z; acc.w += a.w; }
    return acc;
}

// Tail for deg > 8 (40% of nodes take exactly one extra round, deg > 16 rare).
__device__ __forceinline__ void gather_tail(const float4* __restrict__ x4,
                                            const int4* __restrict__ seg,
                                            int c, int half, int l16,
                                            float4& acc) {
    for (int base = 8; base < c; base += 8) {
        int q = base >> 2;
        int4 i0 = __ldg(&seg[q]);
        int4 i1 = __ldg(&seg[q + 1]);
        int e  = base + half;
        int s0 = half ? i0.y : i0.x;
        int s1 = half ? i0.w : i0.z;
        int s2 = half ? i1.y : i1.x;
        int s3 = half ? i1.w : i1.z;
        if (e     < c) { float4 a = __ldg(&x4[s0 * F_VEC4 + l16]);
                         acc.x += a.x; acc.y += a.y; acc.z += a.z; acc.w += a.w; }
        if (e + 2 < c) { float4 a = __ldg(&x4[s1 * F_VEC4 + l16]);
                         acc.x += a.x; acc.y += a.y; acc.z += a.z; acc.w += a.w; }
        if (e + 4 < c) { float4 a = __ldg(&x4[s2 * F_VEC4 + l16]);
                         acc.x += a.x; acc.y += a.y; acc.z += a.z; acc.w += a.w; }
        if (e + 6 < c) { float4 a = __ldg(&x4[s3 * F_VEC4 + l16]);
                         acc.x += a.x; acc.y += a.y; acc.z += a.z; acc.w += a.w; }
    }
}

// ---------------------------------------------------------------------------
// K2: segmented mean, TWO NODES PER WARP (sequential), indices hoisted.
// Both nodes' cursors + first-8 indices load in one hop (6 independent
// loads), then 8 LDG.128 gathers (4 per node) are all in flight together.
// Warp-uniform control flow throughout.
// ---------------------------------------------------------------------------
__global__ void __launch_bounds__(256) k_seg(
        const float4* __restrict__ x4,
        const int* __restrict__ bucket,
        const int* __restrict__ cursor,
        float4* __restrict__ out4,
        int n_nodes) {
    int warp = (blockIdx.x * blockDim.x + threadIdx.x) >> 5;
    int lane = threadIdx.x & 31;
    int half = lane >> 4;
    int l16  = lane & 15;

    int nodeA = warp * 2;
    int nodeB = nodeA + 1;
    if (nodeA >= n_nodes) return;
    bool hasB = nodeB < n_nodes;

    const int4* segA = (const int4*)(bucket + ((size_t)nodeA << CAP_SHIFT));
    const int4* segB = (const int4*)(bucket + ((size_t)nodeB << CAP_SHIFT));

    // hop 1: everything independent
    int  cA  = __ldg(&cursor[nodeA]);
    int4 iA0 = __ldg(&segA[0]);
    int4 iA1 = __ldg(&segA[1]);
    int  cB  = hasB ? __ldg(&cursor[nodeB]) : 0;
    int4 iB0 = hasB ? __ldg(&segB[0]) : make_int4(0,0,0,0);
    int4 iB1 = hasB ? __ldg(&segB[1]) : make_int4(0,0,0,0);

    // hop 2: 8 gathers in flight (4 for A, 4 for B)
    float4 accA = gather8(x4, iA0, iA1, cA, half, l16);
    float4 accB = gather8(x4, iB0, iB1, cB, half, l16);

    if (cA > 8) gather_tail(x4, segA, cA, half, l16, accA);
    if (cB > 8) gather_tail(x4, segB, cB, half, l16, accB);

    // combine halves
    accA.x += __shfl_xor_sync(0xFFFFFFFFu, accA.x, 16);
    accA.y += __shfl_xor_sync(0xFFFFFFFFu, accA.y, 16);
    accA.z += __shfl_xor_sync(0xFFFFFFFFu, accA.z, 16);
    accA.w += __shfl_xor_sync(0xFFFFFFFFu, accA.w, 16);
    accB.x += __shfl_xor_sync(0xFFFFFFFFu, accB.x, 16);
    accB.y += __shfl_xor_sync(0xFFFFFFFFu, accB.y, 16);
    accB.z += __shfl_xor_sync(0xFFFFFFFFu, accB.z, 16);
    accB.w += __shfl_xor_sync(0xFFFFFFFFu, accB.w, 16);

    float wA = 1.0f / (float)(cA > 0 ? cA : 1);
    accA.x *= wA; accA.y *= wA; accA.z *= wA; accA.w *= wA;
    float wB = 1.0f / (float)(cB > 0 ? cB : 1);
    accB.x *= wB; accB.y *= wB; accB.z *= wB; accB.w *= wB;

    // half 0 stores row A, half 1 stores row B: full-warp 512B store
    if (half == 0) {
        out4[nodeA * F_VEC4 + l16] = accA;
    } else if (hasB) {
        out4[nodeB * F_VEC4 + l16] = accB;
    }
}

// ---------------------------------------------------------------------------
// Launch
// ---------------------------------------------------------------------------
extern "C" void kernel_launch(void* const* d_in, const int* in_sizes, int n_in,
                              void* d_out, int out_size) {
    const float* x   = (const float*)d_in[0];
    const int*   src = (const int*)d_in[1];
    const int*   tgt = (const int*)d_in[2];
    float*       out = (float*)d_out;

    int n_nodes  = in_sizes[0] / F_DIM;   // 100000
    int n_edges  = in_sizes[1];           // 800000
    int n_groups = n_edges / 4;

    int *cursor, *bucket;
    cudaGetSymbolAddress((void**)&cursor, g_cursor);
    cudaGetSymbolAddress((void**)&bucket, g_bucket);

    const int B = 256;

    cudaMemsetAsync(cursor, 0, (size_t)n_nodes * sizeof(int));
    {
        int threads_needed = (n_groups + 1) / 2;
        k_sortsrc<<<(threads_needed + B - 1) / B, B>>>(
            (const int4*)src, (const int4*)tgt, cursor, bucket, n_groups);
    }
    {
        // one warp per TWO nodes
        int n_warps = (n_nodes + 1) / 2;
        long long threads = (long long)n_warps * 32;
        int grid = (int)((threads + B - 1) / B);
        k_seg<<<grid, B>>>((const float4*)x, bucket, cursor,
                           (float4*)out, n_nodes);
    }
}

// round 14
// speedup vs baseline: 1.3888x; 1.0995x over previous
#include <cuda_runtime.h>
#include <cstdint>

#define F_DIM 64
#define F_VEC2 32           // 64 floats = 32 float2; lane l owns float2 #l
#define MAX_NODES 100000
#define CAP 64              // bucket capacity per node (deg ~ Poisson(8))
#define CAP_SHIFT 6

// Scratch (no allocation allowed). Zero-initialized. Bucket slots beyond a
// node's degree are never written (degrees identical every launch), so
// speculative gathers through them read row 0 (valid memory, add masked).
// g_cursor is returned to all-zero by k_seg at the end of every launch, so
// no memset pass is needed.
__device__ int g_cursor[MAX_NODES];           // per-node fill cursor == degree
__device__ int g_bucket[MAX_NODES * CAP];     // src ids bucketed by tgt (25.6MB)

// ---------------------------------------------------------------------------
// K1: bucket scatter of src ids by tgt. 8 edges/thread via two int4 pairs.
// start[t] implicit (t*CAP): no count pass, no prefix scan.
// Requires cursor == 0 on entry (guaranteed by initial zero-init + k_seg's
// self-clearing at the end of each launch).
// ---------------------------------------------------------------------------
__global__ void k_sortsrc(const int4* __restrict__ src4,
                          const int4* __restrict__ tgt4,
                          int* __restrict__ cursor,
                          int* __restrict__ bucket,
                          int n_groups) {
    int g = (blockIdx.x * blockDim.x + threadIdx.x) * 2;
    if (g >= n_groups) return;

    int4 s0 = src4[g];
    int4 t0 = tgt4[g];
    bool two = (g + 1) < n_groups;
    int4 s1 = two ? src4[g + 1] : make_int4(0, 0, 0, 0);
    int4 t1 = two ? tgt4[g + 1] : make_int4(0, 0, 0, 0);

    int p0 = atomicAdd(&cursor[t0.x], 1);
    int p1 = atomicAdd(&cursor[t0.y], 1);
    int p2 = atomicAdd(&cursor[t0.z], 1);
    int p3 = atomicAdd(&cursor[t0.w], 1);
    int p4 = two ? atomicAdd(&cursor[t1.x], 1) : 0;
    int p5 = two ? atomicAdd(&cursor[t1.y], 1) : 0;
    int p6 = two ? atomicAdd(&cursor[t1.z], 1) : 0;
    int p7 = two ? atomicAdd(&cursor[t1.w], 1) : 0;

    bucket[(t0.x << CAP_SHIFT) + p0] = s0.x;
    bucket[(t0.y << CAP_SHIFT) + p1] = s0.y;
    bucket[(t0.z << CAP_SHIFT) + p2] = s0.z;
    bucket[(t0.w << CAP_SHIFT) + p3] = s0.w;
    if (two) {
        bucket[(t1.x << CAP_SHIFT) + p4] = s1.x;
        bucket[(t1.y << CAP_SHIFT) + p5] = s1.y;
        bucket[(t1.z << CAP_SHIFT) + p6] = s1.z;
        bucket[(t1.w << CAP_SHIFT) + p7] = s1.w;
    }
}

// ---------------------------------------------------------------------------
// K2: segmented mean. ONE NODE PER WARP, float2 lanes, speculative gathers.
// hop 1: cursor + both index int4s issue together (independent).
// hop 2: 8 unconditional LDG.64 gathers (adds predicated on degree) —
//        no branch between cursor and gathers, 8 loads in flight at only
//        2 regs per load. Warp-uniform control flow throughout.
// Tail loop only for deg > 8 (~40% of nodes, warp-uniform).
// Finally the warp's lane 0 clears cursor[node] for the next launch.
// ---------------------------------------------------------------------------
__global__ void __launch_bounds__(256) k_seg(
        const float2* __restrict__ x2,
        const int* __restrict__ bucket,
        int* __restrict__ cursor,
        float2* __restrict__ out2,
        int n_nodes) {
    int node = (blockIdx.x * blockDim.x + threadIdx.x) >> 5;
    int lane = threadIdx.x & 31;
    if (node >= n_nodes) return;

    const int4* seg = (const int4*)(bucket + ((size_t)node << CAP_SHIFT));

    // hop 1: all independent
    int  c  = __ldg(&cursor[node]);
    int4 i0 = __ldg(&seg[0]);
    int4 i1 = __ldg(&seg[1]);

    // hop 2: 8 speculative gathers (row 0 for unused slots), adds masked
    float2 a0 = __ldg(&x2[i0.x * F_VEC2 + lane]);
    float2 a1 = __ldg(&x2[i0.y * F_VEC2 + lane]);
    float2 a2 = __ldg(&x2[i0.z * F_VEC2 + lane]);
    float2 a3 = __ldg(&x2[i0.w * F_VEC2 + lane]);
    float2 a4 = __ldg(&x2[i1.x * F_VEC2 + lane]);
    float2 a5 = __ldg(&x2[i1.y * F_VEC2 + lane]);
    float2 a6 = __ldg(&x2[i1.z * F_VEC2 + lane]);
    float2 a7 = __ldg(&x2[i1.w * F_VEC2 + lane]);

    float2 acc = make_float2(0.f, 0.f);
    if (c > 0) { acc.x += a0.x; acc.y += a0.y; }
    if (c > 1) { acc.x += a1.x; acc.y += a1.y; }
    if (c > 2) { acc.x += a2.x; acc.y += a2.y; }
    if (c > 3) { acc.x += a3.x; acc.y += a3.y; }
    if (c > 4) { acc.x += a4.x; acc.y += a4.y; }
    if (c > 5) { acc.x += a5.x; acc.y += a5.y; }
    if (c > 6) { acc.x += a6.x; acc.y += a6.y; }
    if (c > 7) { acc.x += a7.x; acc.y += a7.y; }

    // warp-uniform tail for deg > 8
    for (int base = 8; base < c; base += 8) {
        int q = base >> 2;
        int4 j0 = __ldg(&seg[q]);
        int4 j1 = __ldg(&seg[q + 1]);
        if (base + 0 < c) { float2 a = __ldg(&x2[j0.x * F_VEC2 + lane]);
                            acc.x += a.x; acc.y += a.y; }
        if (base + 1 < c) { float2 a = __ldg(&x2[j0.y * F_VEC2 + lane]);
                            acc.x += a.x; acc.y += a.y; }
        if (base + 2 < c) { float2 a = __ldg(&x2[j0.z * F_VEC2 + lane]);
                            acc.x += a.x; acc.y += a.y; }
        if (base + 3 < c) { float2 a = __ldg(&x2[j0.w * F_VEC2 + lane]);
                            acc.x += a.x; acc.y += a.y; }
        if (base + 4 < c) { float2 a = __ldg(&x2[j1.x * F_VEC2 + lane]);
                            acc.x += a.x; acc.y += a.y; }
        if (base + 5 < c) { float2 a = __ldg(&x2[j1.y * F_VEC2 + lane]);
                            acc.x += a.x; acc.y += a.y; }
        if (base + 6 < c) { float2 a = __ldg(&x2[j1.z * F_VEC2 + lane]);
                            acc.x += a.x; acc.y += a.y; }
        if (base + 7 < c) { float2 a = __ldg(&x2[j1.w * F_VEC2 + lane]);
                            acc.x += a.x; acc.y += a.y; }
    }

    float w = 1.0f / (float)(c > 0 ? c : 1);
    acc.x *= w; acc.y *= w;
    out2[node * F_VEC2 + lane] = acc;

    // restore cursor to 0 for the next launch (replaces the memset pass)
    if (lane == 0) cursor[node] = 0;
}

// ---------------------------------------------------------------------------
// Launch
// ---------------------------------------------------------------------------
extern "C" void kernel_launch(void* const* d_in, const int* in_sizes, int n_in,
                              void* d_out, int out_size) {
    const float* x   = (const float*)d_in[0];
    const int*   src = (const int*)d_in[1];
    const int*   tgt = (const int*)d_in[2];
    float*       out = (float*)d_out;

    int n_nodes  = in_sizes[0] / F_DIM;   // 100000
    int n_edges  = in_sizes[1];           // 800000
    int n_groups = n_edges / 4;

    int *cursor, *bucket;
    cudaGetSymbolAddress((void**)&cursor, g_cursor);
    cudaGetSymbolAddress((void**)&bucket, g_bucket);

    const int B = 256;

    // no memset: cursor is zero on first launch (static init) and k_seg
    // returns it to zero at the end of every launch.
    {
        int threads_needed = (n_groups + 1) / 2;
        k_sortsrc<<<(threads_needed + B - 1) / B, B>>>(
            (const int4*)src, (const int4*)tgt, cursor, bucket, n_groups);
    }
    {
        // one warp per node
        long long threads = (long long)n_nodes * 32;
        int grid = (int)((threads + B - 1) / B);
        k_seg<<<grid, B>>>((const float2*)x, bucket, cursor,
                           (float2*)out, n_nodes);
    }
}